// round 15
// baseline (speedup 1.0000x reference)
#include <cuda_runtime.h>
#include <cuda_fp16.h>
#include <cstdint>

#define NB   16
#define NN   20000
#define NE   640000
#define NREG 2000
#define DIN  128
#define FF   32

// ---------------- scratch (device globals; no allocation allowed) ----------
__device__ __half2  g_h16[(size_t)NB * NN * 16];     // 20.5 MB, 64B rows
__device__ __half2  g_rep16[(size_t)NB * NN * 16];   // 20.5 MB, 64B rows
__device__ float    g_eT[(size_t)NE * NB];           // 41 MB: eattr^T [e][b]
__device__ float    g_asrc[NB * NN];
__device__ float    g_adst[NB * NN];
__device__ int      g_src32[NE];
__device__ int      g_dst32[NE];
__device__ int      g_cnt[NN];
__device__ int      g_off[NN + 1];
__device__ int      g_cur[NN];
__device__ unsigned g_sorted[NE];                    // (src<<20)|eid
__device__ int      g_soff[NREG + 1];
__device__ float    g_meanpart[NB][32];
__device__ float    g_mean[NB];
__device__ float    g_c;
__device__ int      g_is64;

// ---------------- helpers ----------------------------------------------------
__device__ __forceinline__ void fma2(unsigned long long& d,
                                     unsigned long long a,
                                     unsigned long long b) {
    asm("fma.rn.f32x2 %0, %1, %2, %0;" : "+l"(d) : "l"(a), "l"(b));
}
__device__ __forceinline__ unsigned long long dup2(float w) {
    unsigned long long r;
    asm("mov.b64 %0, {%1, %1};" : "=l"(r) : "f"(w));
    return r;
}
__device__ __forceinline__ void unpack2(unsigned long long v, float& lo, float& hi) {
    asm("mov.b64 {%0, %1}, %2;" : "=f"(lo), "=f"(hi) : "l"(v));
}
__device__ __forceinline__ void cp_async16(uint32_t smem_dst, const void* gsrc) {
    asm volatile("cp.async.cg.shared.global [%0], [%1], 16;"
                 :: "r"(smem_dst), "l"(gsrc));
}
__device__ __forceinline__ void cp_commit_wait() {
    asm volatile("cp.async.commit_group;");
    asm volatile("cp.async.wait_group 0;");
}

// ---------------- prep: zero cnt, mean partials, scalar c, dtype detect -----
__global__ void k_prep(const float* __restrict__ eattr,
                       const float* __restrict__ lin_edge,
                       const float* __restrict__ att_edge,
                       const int* __restrict__ edge_raw) {
    int tid = threadIdx.x, bx = blockIdx.x, by = blockIdx.y;
    int lane = tid & 31, wid = tid >> 5;

    int id = (by * 32 + bx) * 256 + tid;
    if (id < NN) g_cnt[id] = 0;

    if (bx == 0 && by == 0) {
        if (wid == 0) {
            int any = 0;
            for (int i = lane; i < 1024; i += 32)
                if ((i & 1) && edge_raw[i] != 0) any = 1;
            #pragma unroll
            for (int o = 16; o; o >>= 1) any |= __shfl_xor_sync(0xFFFFFFFFu, any, o);
            if (lane == 0) g_is64 = !any;
        } else if (wid == 1) {
            float p = lin_edge[lane] * att_edge[lane];
            #pragma unroll
            for (int o = 16; o; o >>= 1) p += __shfl_xor_sync(0xFFFFFFFFu, p, o);
            if (lane == 0) g_c = p;
        }
    }

    const float* p = eattr + (size_t)by * NE;
    float s = 0.f;
    for (int i = bx * 256 + tid; i < NE; i += 32 * 256) s += p[i];
    __shared__ float sm[8];
    #pragma unroll
    for (int o = 16; o; o >>= 1) s += __shfl_xor_sync(0xFFFFFFFFu, s, o);
    if (lane == 0) sm[wid] = s;
    __syncthreads();
    if (wid == 0) {
        s = (lane < 8) ? sm[lane] : 0.f;
        #pragma unroll
        for (int o = 4; o; o >>= 1) s += __shfl_xor_sync(0xFFFFFFFFu, s, o);
        if (lane == 0) g_meanpart[by][bx] = s;
    }
}

// ---------------- eattr transpose: g_eT[e][b], 64B rows ---------------------
__global__ void k_trans(const float* __restrict__ eattr) {
    int e = blockIdx.x * 256 + threadIdx.x;
    float v[NB];
    #pragma unroll
    for (int b = 0; b < NB; b++) v[b] = eattr[(size_t)b * NE + e];
    float4* dst = (float4*)(g_eT + (size_t)e * NB);
    #pragma unroll
    for (int t = 0; t < 4; t++)
        dst[t] = make_float4(v[4 * t], v[4 * t + 1], v[4 * t + 2], v[4 * t + 3]);
}

// ---------------- convert indices + histogram -------------------------------
__global__ void k_convert(const void* __restrict__ srcv,
                          const void* __restrict__ dstv) {
    int e = blockIdx.x * blockDim.x + threadIdx.x;
    if (e >= NE) return;
    int s, d;
    if (g_is64) {
        s = (int)((const long long*)srcv)[e];
        d = (int)((const long long*)dstv)[e];
    } else {
        s = ((const int*)srcv)[e];
        d = ((const int*)dstv)[e];
    }
    g_src32[e] = s;
    g_dst32[e] = d;
    atomicAdd(&g_cnt[d], 1);
}

// ---------------- scan + soff + mean finalize (single block, 1024 thr) ------
__global__ void k_scan() {
    __shared__ int tot[1024];
    int t = threadIdx.x;
    int base = t * 20;
    int loc[20];
    int run = 0;
    #pragma unroll
    for (int i = 0; i < 20; i++) {
        int idx = base + i;
        int v = (idx < NN) ? g_cnt[idx] : 0;
        loc[i] = run;
        run += v;
    }
    tot[t] = run;
    __syncthreads();
    for (int off = 1; off < 1024; off <<= 1) {
        int v = (t >= off) ? tot[t - off] : 0;
        __syncthreads();
        tot[t] += v;
        __syncthreads();
    }
    int excl = tot[t] - run;
    #pragma unroll
    for (int i = 0; i < 20; i++) {
        int idx = base + i;
        if (idx < NN) {
            int o = excl + loc[i];
            g_off[idx] = o;
            g_cur[idx] = o;
        }
    }
    if (t == 1023) g_off[NN] = tot[1023];

    for (int r = t; r <= NREG; r += 1024) {
        int lo = 0, hi = NE;
        while (lo < hi) {
            int mid = (lo + hi) >> 1;
            if (g_src32[mid] < r) lo = mid + 1; else hi = mid;
        }
        g_soff[r] = lo;
    }

    if (t < NB) {
        float s = 0.f;
        #pragma unroll
        for (int i = 0; i < 32; i++) s += g_meanpart[t][i];
        g_mean[t] = s * (1.0f / NE);
    }
}

__global__ void k_scatter() {
    int e = blockIdx.x * blockDim.x + threadIdx.x;
    if (e >= NE) return;
    int d = g_dst32[e];
    int pos = atomicAdd(&g_cur[d], 1);
    g_sorted[pos] = ((unsigned)g_src32[e] << 20) | (unsigned)e;
}

// ---------------- GEMM: 2 rows/lane + cp.async (proven R14 config) ----------
__global__ void __launch_bounds__(128)
k_gemm(const float* __restrict__ x, const float* __restrict__ W,
       const float* __restrict__ attS, const float* __restrict__ attD) {
    __shared__ float Ws[DIN * FF];        // 16 KB, row-major [k][f]
    __shared__ float xs[4][64][32];       // 32 KB: per warp 64 rows x 32-k chunk

    int tid = threadIdx.x, wid = tid >> 5, lane = tid & 31;

    #pragma unroll
    for (int i = 0; i < 8; i++)
        ((float4*)Ws)[tid + 128 * i] = ((const float4*)W)[tid + 128 * i];
    __syncthreads();

    size_t rowBase = (size_t)blockIdx.x * 256 + (size_t)wid * 64;
    const float* xg = x + rowBase * DIN;
    uint32_t xs_base = (uint32_t)__cvta_generic_to_shared(&xs[wid][0][0]);

    unsigned long long acc0[16], acc1[16];
    #pragma unroll
    for (int j = 0; j < 16; j++) { acc0[j] = 0ull; acc1[j] = 0ull; }

    #pragma unroll
    for (int kc = 0; kc < 4; kc++) {
        #pragma unroll
        for (int i = 0; i < 16; i++) {
            int idx = i * 32 + lane;
            int row = idx >> 3, seg = idx & 7;
            uint32_t dst = xs_base + (uint32_t)(row * 128 + (((seg + row) & 7) * 16));
            cp_async16(dst, xg + (size_t)row * DIN + kc * 32 + seg * 4);
        }
        cp_commit_wait();
        __syncwarp();

        #pragma unroll
        for (int kj = 0; kj < 8; kj++) {
            int pos = (kj + lane) & 7;
            float4 xv0 = ((const float4*)&xs[wid][lane][0])[pos];
            float4 xv1 = ((const float4*)&xs[wid][lane + 32][0])[pos];
            const float* wbase = Ws + (kc * 32 + kj * 4) * FF;
            #pragma unroll
            for (int dk = 0; dk < 4; dk++) {
                float a0 = dk == 0 ? xv0.x : dk == 1 ? xv0.y : dk == 2 ? xv0.z : xv0.w;
                float a1 = dk == 0 ? xv1.x : dk == 1 ? xv1.y : dk == 2 ? xv1.z : xv1.w;
                unsigned long long xb0 = dup2(a0), xb1 = dup2(a1);
                const ulonglong2* wrow = (const ulonglong2*)(wbase + dk * FF);
                #pragma unroll
                for (int jj = 0; jj < 8; jj++) {
                    ulonglong2 w2 = wrow[jj];
                    fma2(acc0[2 * jj + 0], w2.x, xb0);
                    fma2(acc0[2 * jj + 1], w2.y, xb0);
                    fma2(acc1[2 * jj + 0], w2.x, xb1);
                    fma2(acc1[2 * jj + 1], w2.y, xb1);
                }
            }
        }
        __syncwarp();
    }

    #pragma unroll
    for (int rr = 0; rr < 2; rr++) {
        size_t row = rowBase + lane + 32 * rr;
        float o[32];
        #pragma unroll
        for (int j = 0; j < 16; j++) {
            unsigned long long a = rr ? acc1[j] : acc0[j];
            unpack2(a, o[2 * j], o[2 * j + 1]);
        }
        __half2 hh[16];
        #pragma unroll
        for (int j = 0; j < 16; j++)
            hh[j] = __floats2half2_rn(o[2 * j], o[2 * j + 1]);
        uint4* hp = (uint4*)(g_h16 + row * 16);
        #pragma unroll
        for (int t = 0; t < 4; t++) hp[t] = ((uint4*)hh)[t];

        float vs = 0.f, vd = 0.f;
        #pragma unroll
        for (int t = 0; t < 8; t++) {
            float4 a4 = __ldg(&((const float4*)attS)[t]);
            float4 d4 = __ldg(&((const float4*)attD)[t]);
            vs = fmaf(o[4*t], a4.x, fmaf(o[4*t+1], a4.y, fmaf(o[4*t+2], a4.z, fmaf(o[4*t+3], a4.w, vs))));
            vd = fmaf(o[4*t], d4.x, fmaf(o[4*t+1], d4.y, fmaf(o[4*t+2], d4.z, fmaf(o[4*t+3], d4.w, vd))));
        }
        g_asrc[row] = vs;
        g_adst[row] = vd;
    }
}

// ---------------- k_edge: 4 batches per warp + eT ---------------------------
__device__ __forceinline__ float lrelu(float a) {
    return fmaxf(a, 0.f) + 0.2f * fminf(a, 0.f);
}

__global__ void __launch_bounds__(256)
k_edge(const float* __restrict__ bias) {
    int wid = threadIdx.x >> 5, lane = threadIdx.x & 31;
    int seg = blockIdx.x * 8 + wid;                 // 0 .. (NB/4)*NN-1
    int bq = seg / NN, d = seg - bq * NN;
    int b0 = 4 * bq;

    const float* as0 = g_asrc + (b0 + 0) * NN;
    const float* as1 = g_asrc + (b0 + 1) * NN;
    const float* as2 = g_asrc + (b0 + 2) * NN;
    const float* as3 = g_asrc + (b0 + 3) * NN;
    const __half2* hb = g_h16 + (size_t)b0 * NN * 16;
    float ad0 = g_adst[(b0 + 0) * NN + d];
    float ad1 = g_adst[(b0 + 1) * NN + d];
    float ad2 = g_adst[(b0 + 2) * NN + d];
    float ad3 = g_adst[(b0 + 3) * NN + d];
    float c = g_c;
    int lo = g_off[d], hi = g_off[d + 1];
    int q = lane & 3, g8 = lane >> 2;               // 4 lanes/row, 8 rows/pass

    float ac[4][8];
    #pragma unroll
    for (int j = 0; j < 4; j++)
        #pragma unroll
        for (int k = 0; k < 8; k++) ac[j][k] = 0.f;
    float ss0 = 0.f, ss1 = 0.f, ss2 = 0.f, ss3 = 0.f;

    for (int base = lo; base < hi; base += 32) {
        int m = hi - base;
        if (m > 32) m = 32;
        float ex0 = 0.f, ex1 = 0.f, ex2 = 0.f, ex3 = 0.f;
        int idx = d * 16;
        if (lane < m) {
            unsigned p = __ldcg(&g_sorted[base + lane]);
            int sA = p >> 20;
            int eid = p & 0xFFFFFu;
            float4 ea = __ldcg((const float4*)(g_eT + (size_t)eid * NB + bq * 4));
            ex0 = __expf(lrelu(as0[sA] + ad0 + c * ea.x));
            ex1 = __expf(lrelu(as1[sA] + ad1 + c * ea.y));
            ex2 = __expf(lrelu(as2[sA] + ad2 + c * ea.z));
            ex3 = __expf(lrelu(as3[sA] + ad3 + c * ea.w));
            idx = sA * 16;
        }
        ss0 += ex0; ss1 += ex1; ss2 += ex2; ss3 += ex3;

        #pragma unroll
        for (int t = 0; t < 4; t++) {
            int jj = 8 * t + g8;
            int   it = __shfl_sync(0xFFFFFFFFu, idx, jj);
            float e0 = __shfl_sync(0xFFFFFFFFu, ex0, jj);
            float e1 = __shfl_sync(0xFFFFFFFFu, ex1, jj);
            float e2 = __shfl_sync(0xFFFFFFFFu, ex2, jj);
            float e3 = __shfl_sync(0xFFFFFFFFu, ex3, jj);
            uint4 r0 = *(const uint4*)(hb + 0 * (size_t)NN * 16 + it + q * 4);
            uint4 r1 = *(const uint4*)(hb + 1 * (size_t)NN * 16 + it + q * 4);
            uint4 r2 = *(const uint4*)(hb + 2 * (size_t)NN * 16 + it + q * 4);
            uint4 r3 = *(const uint4*)(hb + 3 * (size_t)NN * 16 + it + q * 4);
            const __half2* h0 = (const __half2*)&r0;
            const __half2* h1 = (const __half2*)&r1;
            const __half2* h2 = (const __half2*)&r2;
            const __half2* h3 = (const __half2*)&r3;
            #pragma unroll
            for (int k = 0; k < 4; k++) {
                float2 f0 = __half22float2(h0[k]);
                float2 f1 = __half22float2(h1[k]);
                float2 f2 = __half22float2(h2[k]);
                float2 f3 = __half22float2(h3[k]);
                ac[0][2*k+0] = fmaf(e0, f0.x, ac[0][2*k+0]);
                ac[0][2*k+1] = fmaf(e0, f0.y, ac[0][2*k+1]);
                ac[1][2*k+0] = fmaf(e1, f1.x, ac[1][2*k+0]);
                ac[1][2*k+1] = fmaf(e1, f1.y, ac[1][2*k+1]);
                ac[2][2*k+0] = fmaf(e2, f2.x, ac[2][2*k+0]);
                ac[2][2*k+1] = fmaf(e2, f2.y, ac[2][2*k+1]);
                ac[3][2*k+0] = fmaf(e3, f3.x, ac[3][2*k+0]);
                ac[3][2*k+1] = fmaf(e3, f3.y, ac[3][2*k+1]);
            }
        }
    }

    float exs[4], inv[4];
    exs[0] = __expf(lrelu(as0[d] + ad0 + c * g_mean[b0 + 0]));
    exs[1] = __expf(lrelu(as1[d] + ad1 + c * g_mean[b0 + 1]));
    exs[2] = __expf(lrelu(as2[d] + ad2 + c * g_mean[b0 + 2]));
    exs[3] = __expf(lrelu(as3[d] + ad3 + c * g_mean[b0 + 3]));
    #pragma unroll
    for (int o = 16; o; o >>= 1) {
        ss0 += __shfl_xor_sync(0xFFFFFFFFu, ss0, o);
        ss1 += __shfl_xor_sync(0xFFFFFFFFu, ss1, o);
        ss2 += __shfl_xor_sync(0xFFFFFFFFu, ss2, o);
        ss3 += __shfl_xor_sync(0xFFFFFFFFu, ss3, o);
    }
    inv[0] = 1.f / (ss0 + exs[0]);
    inv[1] = 1.f / (ss1 + exs[1]);
    inv[2] = 1.f / (ss2 + exs[2]);
    inv[3] = 1.f / (ss3 + exs[3]);

    #pragma unroll
    for (int o = 4; o <= 16; o <<= 1)
        #pragma unroll
        for (int j = 0; j < 4; j++)
            #pragma unroll
            for (int k = 0; k < 8; k++)
                ac[j][k] += __shfl_xor_sync(0xFFFFFFFFu, ac[j][k], o);

    if (lane < 4) {
        float2 bq2[4];
        #pragma unroll
        for (int k = 0; k < 4; k++) bq2[k] = ((const float2*)bias)[q * 4 + k];
        #pragma unroll
        for (int j = 0; j < 4; j++) {
            uint4 sr = *(const uint4*)(hb + (size_t)j * NN * 16 + d * 16 + q * 4);
            const __half2* sh = (const __half2*)&sr;
            __half2 oo[4];
            #pragma unroll
            for (int k = 0; k < 4; k++) {
                float2 f = __half22float2(sh[k]);
                float rx = fmaf(exs[j], f.x, ac[j][2*k+0]) * inv[j] + bq2[k].x;
                float ry = fmaf(exs[j], f.y, ac[j][2*k+1]) * inv[j] + bq2[k].y;
                oo[k] = __floats2half2_rn(rx, ry);
            }
            *(uint4*)(g_rep16 + ((size_t)(b0 + j) * NN + d) * 16 + q * 4) = *(uint4*)oo;
        }
    }
}

// ---------------- k_pool: 4 batches per warp --------------------------------
__global__ void __launch_bounds__(256)
k_pool(float* __restrict__ out) {
    int wid = threadIdx.x >> 5, lane = threadIdx.x & 31;
    int seg = blockIdx.x * 8 + wid;                 // 0 .. (NB/4)*NREG-1
    int bq = seg / NREG, r = seg - bq * NREG;
    int b0 = 4 * bq;
    int lo = g_soff[r], hi = g_soff[r + 1];
    const __half2* rb = g_rep16 + (size_t)b0 * NN * 16;
    int q = lane & 3, g8 = lane >> 2;

    float ac[4][8];
    #pragma unroll
    for (int j = 0; j < 4; j++)
        #pragma unroll
        for (int k = 0; k < 8; k++) ac[j][k] = 0.f;

    for (int base = lo; base < hi; base += 32) {
        int m = hi - base;
        if (m > 32) m = 32;
        int idx = (lane < m) ? __ldcg(&g_dst32[base + lane]) * 16 : -1;
        #pragma unroll
        for (int t = 0; t < 4; t++) {
            int it = __shfl_sync(0xFFFFFFFFu, idx, 8 * t + g8);
            if (it >= 0) {
                uint4 r0 = *(const uint4*)(rb + 0 * (size_t)NN * 16 + it + q * 4);
                uint4 r1 = *(const uint4*)(rb + 1 * (size_t)NN * 16 + it + q * 4);
                uint4 r2 = *(const uint4*)(rb + 2 * (size_t)NN * 16 + it + q * 4);
                uint4 r3 = *(const uint4*)(rb + 3 * (size_t)NN * 16 + it + q * 4);
                const __half2* h0 = (const __half2*)&r0;
                const __half2* h1 = (const __half2*)&r1;
                const __half2* h2 = (const __half2*)&r2;
                const __half2* h3 = (const __half2*)&r3;
                #pragma unroll
                for (int k = 0; k < 4; k++) {
                    float2 f0 = __half22float2(h0[k]);
                    float2 f1 = __half22float2(h1[k]);
                    float2 f2 = __half22float2(h2[k]);
                    float2 f3 = __half22float2(h3[k]);
                    ac[0][2*k+0] += f0.x; ac[0][2*k+1] += f0.y;
                    ac[1][2*k+0] += f1.x; ac[1][2*k+1] += f1.y;
                    ac[2][2*k+0] += f2.x; ac[2][2*k+1] += f2.y;
                    ac[3][2*k+0] += f3.x; ac[3][2*k+1] += f3.y;
                }
            }
        }
    }

    #pragma unroll
    for (int o = 4; o <= 16; o <<= 1)
        #pragma unroll
        for (int j = 0; j < 4; j++)
            #pragma unroll
            for (int k = 0; k < 8; k++)
                ac[j][k] += __shfl_xor_sync(0xFFFFFFFFu, ac[j][k], o);

    if (lane < 4) {
        #pragma unroll
        for (int j = 0; j < 4; j++) {
            uint4 sr = *(const uint4*)(rb + (size_t)j * NN * 16 + (size_t)r * 16 + q * 4);
            const __half2* sh = (const __half2*)&sr;
            float o8[8];
            #pragma unroll
            for (int k = 0; k < 4; k++) {
                float2 f = __half22float2(sh[k]);
                o8[2*k+0] = ac[j][2*k+0] + f.x;
                o8[2*k+1] = ac[j][2*k+1] + f.y;
            }
            float* op = out + ((size_t)(b0 + j) * NREG + r) * FF + q * 8;
            *(float4*)(op + 0) = make_float4(o8[0], o8[1], o8[2], o8[3]);
            *(float4*)(op + 4) = make_float4(o8[4], o8[5], o8[6], o8[7]);
        }
    }
}

// ---------------- launch ---------------------------------------------------
extern "C" void kernel_launch(void* const* d_in, const int* in_sizes, int n_in,
                              void* d_out, int out_size) {
    const float* x        = (const float*)d_in[0];
    const float* edgeattr = (const float*)d_in[1];
    const float* W        = (const float*)d_in[2];
    const float* att_src  = (const float*)d_in[3];
    const float* att_dst  = (const float*)d_in[4];
    const float* lin_edge = (const float*)d_in[5];
    const float* att_edge = (const float*)d_in[6];
    const float* bias     = (const float*)d_in[7];
    const void*  esrc     = d_in[8];
    const void*  edst     = d_in[9];
    float* out = (float*)d_out;

    k_prep<<<dim3(32, NB), 256>>>(edgeattr, lin_edge, att_edge, (const int*)edst);
    k_convert<<<NE / 256, 256>>>(esrc, edst);
    k_trans<<<NE / 256, 256>>>(edgeattr);
    k_gemm<<<(NB * NN) / 256, 128>>>(x, W, att_src, att_dst); // 4th: profiled
    k_scan<<<1, 1024>>>();
    k_scatter<<<NE / 256, 256>>>();
    k_edge<<<(NB / 4 * NN) / 8, 256>>>(bias);
    k_pool<<<(NB / 4 * NREG) / 8, 256>>>(out);
}

// round 16
// speedup vs baseline: 1.1969x; 1.1969x over previous
#include <cuda_runtime.h>
#include <cuda_fp16.h>
#include <cstdint>

#define NB   16
#define NN   20000
#define NE   640000
#define NREG 2000
#define DIN  128
#define FF   32

// ---------------- scratch (device globals; no allocation allowed) ----------
__device__ __half2  g_h16[(size_t)NB * NN * 16];     // 20.5 MB, 64B rows
__device__ __half2  g_rep16[(size_t)NB * NN * 16];   // 20.5 MB, 64B rows
__device__ float    g_asrc[NB * NN];
__device__ float    g_adst[NB * NN];
__device__ int      g_src32[NE];
__device__ int      g_dst32[NE];
__device__ int      g_cnt[NN];
__device__ int      g_off[NN + 1];
__device__ int      g_cur[NN];
__device__ unsigned g_sorted[NE];                    // (src<<20)|eid
__device__ int      g_soff[NREG + 1];
__device__ float    g_meanpart[NB][32];
__device__ float    g_mean[NB];
__device__ float    g_c;
__device__ int      g_is64;

// ---------------- helpers ----------------------------------------------------
__device__ __forceinline__ void fma2(unsigned long long& d,
                                     unsigned long long a,
                                     unsigned long long b) {
    asm("fma.rn.f32x2 %0, %1, %2, %0;" : "+l"(d) : "l"(a), "l"(b));
}
__device__ __forceinline__ unsigned long long dup2(float w) {
    unsigned long long r;
    asm("mov.b64 %0, {%1, %1};" : "=l"(r) : "f"(w));
    return r;
}
__device__ __forceinline__ void unpack2(unsigned long long v, float& lo, float& hi) {
    asm("mov.b64 {%0, %1}, %2;" : "=f"(lo), "=f"(hi) : "l"(v));
}
__device__ __forceinline__ void cp_async16(uint32_t smem_dst, const void* gsrc) {
    asm volatile("cp.async.cg.shared.global [%0], [%1], 16;"
                 :: "r"(smem_dst), "l"(gsrc));
}
__device__ __forceinline__ void cp_commit_wait() {
    asm volatile("cp.async.commit_group;");
    asm volatile("cp.async.wait_group 0;");
}

// ---------------- prep: zero cnt, mean partials, scalar c, dtype detect -----
__global__ void k_prep(const float* __restrict__ eattr,
                       const float* __restrict__ lin_edge,
                       const float* __restrict__ att_edge,
                       const int* __restrict__ edge_raw) {
    int tid = threadIdx.x, bx = blockIdx.x, by = blockIdx.y;
    int lane = tid & 31, wid = tid >> 5;

    int id = (by * 32 + bx) * 256 + tid;
    if (id < NN) g_cnt[id] = 0;

    if (bx == 0 && by == 0) {
        if (wid == 0) {
            int any = 0;
            for (int i = lane; i < 1024; i += 32)
                if ((i & 1) && edge_raw[i] != 0) any = 1;
            #pragma unroll
            for (int o = 16; o; o >>= 1) any |= __shfl_xor_sync(0xFFFFFFFFu, any, o);
            if (lane == 0) g_is64 = !any;
        } else if (wid == 1) {
            float p = lin_edge[lane] * att_edge[lane];
            #pragma unroll
            for (int o = 16; o; o >>= 1) p += __shfl_xor_sync(0xFFFFFFFFu, p, o);
            if (lane == 0) g_c = p;
        }
    }

    const float* p = eattr + (size_t)by * NE;
    float s = 0.f;
    for (int i = bx * 256 + tid; i < NE; i += 32 * 256) s += p[i];
    __shared__ float sm[8];
    #pragma unroll
    for (int o = 16; o; o >>= 1) s += __shfl_xor_sync(0xFFFFFFFFu, s, o);
    if (lane == 0) sm[wid] = s;
    __syncthreads();
    if (wid == 0) {
        s = (lane < 8) ? sm[lane] : 0.f;
        #pragma unroll
        for (int o = 4; o; o >>= 1) s += __shfl_xor_sync(0xFFFFFFFFu, s, o);
        if (lane == 0) g_meanpart[by][bx] = s;
    }
}

// ---------------- convert indices + histogram -------------------------------
__global__ void k_convert(const void* __restrict__ srcv,
                          const void* __restrict__ dstv) {
    int e = blockIdx.x * blockDim.x + threadIdx.x;
    if (e >= NE) return;
    int s, d;
    if (g_is64) {
        s = (int)((const long long*)srcv)[e];
        d = (int)((const long long*)dstv)[e];
    } else {
        s = ((const int*)srcv)[e];
        d = ((const int*)dstv)[e];
    }
    g_src32[e] = s;
    g_dst32[e] = d;
    atomicAdd(&g_cnt[d], 1);
}

// ---------------- scan + soff + mean finalize (single block, 1024 thr) ------
__global__ void k_scan() {
    __shared__ int tot[1024];
    int t = threadIdx.x;
    int base = t * 20;
    int loc[20];
    int run = 0;
    #pragma unroll
    for (int i = 0; i < 20; i++) {
        int idx = base + i;
        int v = (idx < NN) ? g_cnt[idx] : 0;
        loc[i] = run;
        run += v;
    }
    tot[t] = run;
    __syncthreads();
    for (int off = 1; off < 1024; off <<= 1) {
        int v = (t >= off) ? tot[t - off] : 0;
        __syncthreads();
        tot[t] += v;
        __syncthreads();
    }
    int excl = tot[t] - run;
    #pragma unroll
    for (int i = 0; i < 20; i++) {
        int idx = base + i;
        if (idx < NN) {
            int o = excl + loc[i];
            g_off[idx] = o;
            g_cur[idx] = o;
        }
    }
    if (t == 1023) g_off[NN] = tot[1023];

    for (int r = t; r <= NREG; r += 1024) {
        int lo = 0, hi = NE;
        while (lo < hi) {
            int mid = (lo + hi) >> 1;
            if (g_src32[mid] < r) lo = mid + 1; else hi = mid;
        }
        g_soff[r] = lo;
    }

    if (t < NB) {
        float s = 0.f;
        #pragma unroll
        for (int i = 0; i < 32; i++) s += g_meanpart[t][i];
        g_mean[t] = s * (1.0f / NE);
    }
}

__global__ void k_scatter() {
    int e = blockIdx.x * blockDim.x + threadIdx.x;
    if (e >= NE) return;
    int d = g_dst32[e];
    int pos = atomicAdd(&g_cur[d], 1);
    g_sorted[pos] = ((unsigned)g_src32[e] << 20) | (unsigned)e;
}

// ---------------- GEMM: 2 rows/lane + cp.async, 3 blocks/SM -----------------
__global__ void __launch_bounds__(128, 3)
k_gemm(const float* __restrict__ x, const float* __restrict__ W,
       const float* __restrict__ attS, const float* __restrict__ attD) {
    __shared__ float Ws[DIN * FF];        // 16 KB, row-major [k][f]
    __shared__ float xs[4][64][32];       // 32 KB: per warp 64 rows x 32-k chunk

    int tid = threadIdx.x, wid = tid >> 5, lane = tid & 31;

    #pragma unroll
    for (int i = 0; i < 8; i++)
        ((float4*)Ws)[tid + 128 * i] = ((const float4*)W)[tid + 128 * i];
    __syncthreads();

    size_t rowBase = (size_t)blockIdx.x * 256 + (size_t)wid * 64;
    const float* xg = x + rowBase * DIN;
    uint32_t xs_base = (uint32_t)__cvta_generic_to_shared(&xs[wid][0][0]);

    unsigned long long acc0[16], acc1[16];
    #pragma unroll
    for (int j = 0; j < 16; j++) { acc0[j] = 0ull; acc1[j] = 0ull; }

    #pragma unroll
    for (int kc = 0; kc < 4; kc++) {
        #pragma unroll
        for (int i = 0; i < 16; i++) {
            int idx = i * 32 + lane;
            int row = idx >> 3, seg = idx & 7;
            uint32_t dst = xs_base + (uint32_t)(row * 128 + (((seg + row) & 7) * 16));
            cp_async16(dst, xg + (size_t)row * DIN + kc * 32 + seg * 4);
        }
        cp_commit_wait();
        __syncwarp();

        #pragma unroll
        for (int kj = 0; kj < 8; kj++) {
            int pos = (kj + lane) & 7;
            float4 xv0 = ((const float4*)&xs[wid][lane][0])[pos];
            float4 xv1 = ((const float4*)&xs[wid][lane + 32][0])[pos];
            const float* wbase = Ws + (kc * 32 + kj * 4) * FF;
            #pragma unroll
            for (int dk = 0; dk < 4; dk++) {
                float a0 = dk == 0 ? xv0.x : dk == 1 ? xv0.y : dk == 2 ? xv0.z : xv0.w;
                float a1 = dk == 0 ? xv1.x : dk == 1 ? xv1.y : dk == 2 ? xv1.z : xv1.w;
                unsigned long long xb0 = dup2(a0), xb1 = dup2(a1);
                const ulonglong2* wrow = (const ulonglong2*)(wbase + dk * FF);
                #pragma unroll
                for (int jj = 0; jj < 8; jj++) {
                    ulonglong2 w2 = wrow[jj];
                    fma2(acc0[2 * jj + 0], w2.x, xb0);
                    fma2(acc0[2 * jj + 1], w2.y, xb0);
                    fma2(acc1[2 * jj + 0], w2.x, xb1);
                    fma2(acc1[2 * jj + 1], w2.y, xb1);
                }
            }
        }
        __syncwarp();
    }

    #pragma unroll
    for (int rr = 0; rr < 2; rr++) {
        size_t row = rowBase + lane + 32 * rr;
        float o[32];
        #pragma unroll
        for (int j = 0; j < 16; j++) {
            unsigned long long a = rr ? acc1[j] : acc0[j];
            unpack2(a, o[2 * j], o[2 * j + 1]);
        }
        __half2 hh[16];
        #pragma unroll
        for (int j = 0; j < 16; j++)
            hh[j] = __floats2half2_rn(o[2 * j], o[2 * j + 1]);
        uint4* hp = (uint4*)(g_h16 + row * 16);
        #pragma unroll
        for (int t = 0; t < 4; t++) hp[t] = ((uint4*)hh)[t];

        float vs = 0.f, vd = 0.f;
        #pragma unroll
        for (int t = 0; t < 8; t++) {
            float4 a4 = __ldg(&((const float4*)attS)[t]);
            float4 d4 = __ldg(&((const float4*)attD)[t]);
            vs = fmaf(o[4*t], a4.x, fmaf(o[4*t+1], a4.y, fmaf(o[4*t+2], a4.z, fmaf(o[4*t+3], a4.w, vs))));
            vd = fmaf(o[4*t], d4.x, fmaf(o[4*t+1], d4.y, fmaf(o[4*t+2], d4.z, fmaf(o[4*t+3], d4.w, vd))));
        }
        g_asrc[row] = vs;
        g_adst[row] = vd;
    }
}

// ---------------- k_edge: 2 batches per warp, shared segment indices --------
__device__ __forceinline__ float lrelu(float a) {
    return fmaxf(a, 0.f) + 0.2f * fminf(a, 0.f);
}

__global__ void __launch_bounds__(256)
k_edge(const float* __restrict__ eattr, const float* __restrict__ bias) {
    int wid = threadIdx.x >> 5, lane = threadIdx.x & 31;
    int seg = blockIdx.x * 8 + wid;                 // 0 .. (NB/2)*NN-1
    int bp = seg / NN, d = seg - bp * NN;
    int b0 = 2 * bp;

    const float* asb0 = g_asrc + b0 * NN;
    const float* asb1 = asb0 + NN;
    const float* eab0 = eattr + (size_t)b0 * NE;
    const float* eab1 = eab0 + NE;
    const __half2* hb0 = g_h16 + (size_t)b0 * NN * 16;
    const __half2* hb1 = hb0 + (size_t)NN * 16;
    float ad0 = g_adst[b0 * NN + d];
    float ad1 = g_adst[(b0 + 1) * NN + d];
    float c = g_c;
    int lo = g_off[d], hi = g_off[d + 1];
    int q = lane & 3, g8 = lane >> 2;               // 4 lanes/row, 8 rows/pass

    float ac0[8] = {0.f, 0.f, 0.f, 0.f, 0.f, 0.f, 0.f, 0.f};
    float ac1[8] = {0.f, 0.f, 0.f, 0.f, 0.f, 0.f, 0.f, 0.f};
    float ss0 = 0.f, ss1 = 0.f;

    for (int base = lo; base < hi; base += 32) {
        int m = hi - base;
        if (m > 32) m = 32;
        float ex0 = 0.f, ex1 = 0.f;
        int idx = d * 16;
        if (lane < m) {
            unsigned p = __ldcg(&g_sorted[base + lane]);
            int sA = p >> 20;
            int eid = p & 0xFFFFFu;
            float asA0 = asb0[sA], asA1 = asb1[sA];
            float e0 = __ldcg(&eab0[eid]);
            float e1 = __ldcg(&eab1[eid]);
            ex0 = __expf(lrelu(asA0 + ad0 + c * e0));
            ex1 = __expf(lrelu(asA1 + ad1 + c * e1));
            idx = sA * 16;
        }
        ss0 += ex0;
        ss1 += ex1;

        float e40[4], e41[4];
        int   i4[4];
        #pragma unroll
        for (int t = 0; t < 4; t++) {
            int j = 8 * t + g8;
            e40[t] = __shfl_sync(0xFFFFFFFFu, ex0, j);
            e41[t] = __shfl_sync(0xFFFFFFFFu, ex1, j);
            i4[t]  = __shfl_sync(0xFFFFFFFFu, idx, j);
        }
        uint4 r0[4], r1[4];
        #pragma unroll
        for (int t = 0; t < 4; t++) {
            r0[t] = *(const uint4*)(hb0 + i4[t] + q * 4);
            r1[t] = *(const uint4*)(hb1 + i4[t] + q * 4);
        }
        #pragma unroll
        for (int t = 0; t < 4; t++) {
            const __half2* h0 = (const __half2*)&r0[t];
            const __half2* h1 = (const __half2*)&r1[t];
            float e0 = e40[t], e1 = e41[t];
            #pragma unroll
            for (int k = 0; k < 4; k++) {
                float2 f0 = __half22float2(h0[k]);
                float2 f1 = __half22float2(h1[k]);
                ac0[2 * k + 0] = fmaf(e0, f0.x, ac0[2 * k + 0]);
                ac0[2 * k + 1] = fmaf(e0, f0.y, ac0[2 * k + 1]);
                ac1[2 * k + 0] = fmaf(e1, f1.x, ac1[2 * k + 0]);
                ac1[2 * k + 1] = fmaf(e1, f1.y, ac1[2 * k + 1]);
            }
        }
    }

    float exs0 = __expf(lrelu(asb0[d] + ad0 + c * g_mean[b0]));
    float exs1 = __expf(lrelu(asb1[d] + ad1 + c * g_mean[b0 + 1]));
    #pragma unroll
    for (int o = 16; o; o >>= 1) {
        ss0 += __shfl_xor_sync(0xFFFFFFFFu, ss0, o);
        ss1 += __shfl_xor_sync(0xFFFFFFFFu, ss1, o);
    }
    float inv0 = 1.f / (ss0 + exs0);
    float inv1 = 1.f / (ss1 + exs1);

    #pragma unroll
    for (int o = 4; o <= 16; o <<= 1) {
        #pragma unroll
        for (int k = 0; k < 8; k++) {
            ac0[k] += __shfl_xor_sync(0xFFFFFFFFu, ac0[k], o);
            ac1[k] += __shfl_xor_sync(0xFFFFFFFFu, ac1[k], o);
        }
    }

    if (lane < 4) {
        float2 bq[4];
        #pragma unroll
        for (int k = 0; k < 4; k++) bq[k] = ((const float2*)bias)[q * 4 + k];

        uint4 s0 = *(const uint4*)(hb0 + d * 16 + q * 4);
        uint4 s1 = *(const uint4*)(hb1 + d * 16 + q * 4);
        const __half2* sh0 = (const __half2*)&s0;
        const __half2* sh1 = (const __half2*)&s1;
        __half2 o0[4], o1[4];
        #pragma unroll
        for (int k = 0; k < 4; k++) {
            float2 f0 = __half22float2(sh0[k]);
            float2 f1 = __half22float2(sh1[k]);
            float r0x = fmaf(exs0, f0.x, ac0[2 * k + 0]) * inv0 + bq[k].x;
            float r0y = fmaf(exs0, f0.y, ac0[2 * k + 1]) * inv0 + bq[k].y;
            float r1x = fmaf(exs1, f1.x, ac1[2 * k + 0]) * inv1 + bq[k].x;
            float r1y = fmaf(exs1, f1.y, ac1[2 * k + 1]) * inv1 + bq[k].y;
            o0[k] = __floats2half2_rn(r0x, r0y);
            o1[k] = __floats2half2_rn(r1x, r1y);
        }
        *(uint4*)(g_rep16 + ((size_t)b0 * NN + d) * 16 + q * 4) = *(uint4*)o0;
        *(uint4*)(g_rep16 + ((size_t)(b0 + 1) * NN + d) * 16 + q * 4) = *(uint4*)o1;
    }
}

// ---------------- k_pool: 2 batches per warp --------------------------------
__global__ void __launch_bounds__(256)
k_pool(float* __restrict__ out) {
    int wid = threadIdx.x >> 5, lane = threadIdx.x & 31;
    int seg = blockIdx.x * 8 + wid;                 // 0 .. (NB/2)*NREG-1
    int bp = seg / NREG, r = seg - bp * NREG;
    int b0 = 2 * bp;
    int lo = g_soff[r], hi = g_soff[r + 1];
    const __half2* rb0 = g_rep16 + (size_t)b0 * NN * 16;
    const __half2* rb1 = rb0 + (size_t)NN * 16;
    int q = lane & 3, g8 = lane >> 2;

    float ac0[8] = {0.f, 0.f, 0.f, 0.f, 0.f, 0.f, 0.f, 0.f};
    float ac1[8] = {0.f, 0.f, 0.f, 0.f, 0.f, 0.f, 0.f, 0.f};

    for (int base = lo; base < hi; base += 32) {
        int m = hi - base;
        if (m > 32) m = 32;
        int idx = (lane < m) ? __ldcg(&g_dst32[base + lane]) * 16 : -1;
        int i4[4];
        #pragma unroll
        for (int t = 0; t < 4; t++)
            i4[t] = __shfl_sync(0xFFFFFFFFu, idx, 8 * t + g8);
        #pragma unroll
        for (int t = 0; t < 4; t++) {
            if (i4[t] >= 0) {
                uint4 r0 = *(const uint4*)(rb0 + i4[t] + q * 4);
                uint4 r1 = *(const uint4*)(rb1 + i4[t] + q * 4);
                const __half2* h0 = (const __half2*)&r0;
                const __half2* h1 = (const __half2*)&r1;
                #pragma unroll
                for (int k = 0; k < 4; k++) {
                    float2 f0 = __half22float2(h0[k]);
                    float2 f1 = __half22float2(h1[k]);
                    ac0[2 * k + 0] += f0.x; ac0[2 * k + 1] += f0.y;
                    ac1[2 * k + 0] += f1.x; ac1[2 * k + 1] += f1.y;
                }
            }
        }
    }

    #pragma unroll
    for (int o = 4; o <= 16; o <<= 1) {
        #pragma unroll
        for (int k = 0; k < 8; k++) {
            ac0[k] += __shfl_xor_sync(0xFFFFFFFFu, ac0[k], o);
            ac1[k] += __shfl_xor_sync(0xFFFFFFFFu, ac1[k], o);
        }
    }

    if (lane < 4) {
        uint4 s0 = *(const uint4*)(rb0 + (size_t)r * 16 + q * 4);
        uint4 s1 = *(const uint4*)(rb1 + (size_t)r * 16 + q * 4);
        const __half2* sh0 = (const __half2*)&s0;
        const __half2* sh1 = (const __half2*)&s1;
        float o0[8], o1[8];
        #pragma unroll
        for (int k = 0; k < 4; k++) {
            float2 f0 = __half22float2(sh0[k]);
            float2 f1 = __half22float2(sh1[k]);
            o0[2 * k + 0] = ac0[2 * k + 0] + f0.x;
            o0[2 * k + 1] = ac0[2 * k + 1] + f0.y;
            o1[2 * k + 0] = ac1[2 * k + 0] + f1.x;
            o1[2 * k + 1] = ac1[2 * k + 1] + f1.y;
        }
        float* op0 = out + ((size_t)b0 * NREG + r) * FF + q * 8;
        float* op1 = out + ((size_t)(b0 + 1) * NREG + r) * FF + q * 8;
        *(float4*)(op0 + 0) = make_float4(o0[0], o0[1], o0[2], o0[3]);
        *(float4*)(op0 + 4) = make_float4(o0[4], o0[5], o0[6], o0[7]);
        *(float4*)(op1 + 0) = make_float4(o1[0], o1[1], o1[2], o1[3]);
        *(float4*)(op1 + 4) = make_float4(o1[4], o1[5], o1[6], o1[7]);
    }
}

// ---------------- launch ---------------------------------------------------
extern "C" void kernel_launch(void* const* d_in, const int* in_sizes, int n_in,
                              void* d_out, int out_size) {
    const float* x        = (const float*)d_in[0];
    const float* edgeattr = (const float*)d_in[1];
    const float* W        = (const float*)d_in[2];
    const float* att_src  = (const float*)d_in[3];
    const float* att_dst  = (const float*)d_in[4];
    const float* lin_edge = (const float*)d_in[5];
    const float* att_edge = (const float*)d_in[6];
    const float* bias     = (const float*)d_in[7];
    const void*  esrc     = d_in[8];
    const void*  edst     = d_in[9];
    float* out = (float*)d_out;

    k_prep<<<dim3(32, NB), 256>>>(edgeattr, lin_edge, att_edge, (const int*)edst);
    k_convert<<<NE / 256, 256>>>(esrc, edst);
    k_scan<<<1, 1024>>>();
    k_gemm<<<(NB * NN) / 256, 128>>>(x, W, att_src, att_dst); // 4th: profiled
    k_scatter<<<NE / 256, 256>>>();
    k_edge<<<(NB / 2 * NN) / 8, 256>>>(edgeattr, bias);
    k_pool<<<(NB / 2 * NREG) / 8, 256>>>(out);
}